// round 7
// baseline (speedup 1.0000x reference)
#include <cuda_runtime.h>
#include <math.h>

#define VOCAB 50000
#define D 300
#define S 5
#define CTX 10
#define B 16384
#define XCOLS (2 + CTX)

#define THREADS 256
#define EPW 2                                   // batch elements per warp
#define NBLOCKS ((B / EPW) * 32 / THREADS)      // 1024 blocks

// Zero at module load; finalize resets after each read -> graph-replay safe.
__device__ float g_acc[S];

__global__ __launch_bounds__(THREADS) void sense_main_kernel(
    const int* __restrict__ x,
    const float* __restrict__ Wg,
    const float* __restrict__ Ws)
{
    const int gwarp = (blockIdx.x * THREADS + threadIdx.x) >> 5;
    const int lane  = threadIdx.x & 31;

    __shared__ float ssum[S];
    if (threadIdx.x < S) ssum[threadIdx.x] = 0.0f;
    __syncthreads();

    float sc[S];

    {
        const int* xr0 = x + (size_t)(gwarp * EPW) * XCOLS;
        const int* xr1 = xr0 + XCOLS;
        const int xa = __ldg(&xr0[0]);
        const int xb = __ldg(&xr1[0]);

        const bool has3 = (lane + 64) < 75;   // 75 float4 chunks per 300-float row

        // context accumulators for both elements (24 regs)
        float4 a0 = make_float4(0.f,0.f,0.f,0.f), a1 = a0, a2 = a0;
        float4 b0 = a0, b1 = a0, b2 = a0;

        #pragma unroll
        for (int j = 0; j < CTX; j++) {
            const int wa = __ldg(&xr0[2 + j]);
            const int wb = __ldg(&xr1[2 + j]);
            const float4* ra = (const float4*)(Wg + (size_t)wa * D);
            const float4* rb = (const float4*)(Wg + (size_t)wb * D);
            float4 ta0 = ra[lane];
            float4 tb0 = rb[lane];
            float4 ta1 = ra[lane + 32];
            float4 tb1 = rb[lane + 32];
            a0.x += ta0.x; a0.y += ta0.y; a0.z += ta0.z; a0.w += ta0.w;
            b0.x += tb0.x; b0.y += tb0.y; b0.z += tb0.z; b0.w += tb0.w;
            a1.x += ta1.x; a1.y += ta1.y; a1.z += ta1.z; a1.w += ta1.w;
            b1.x += tb1.x; b1.y += tb1.y; b1.z += tb1.z; b1.w += tb1.w;
            if (has3) {
                float4 ta2 = ra[lane + 64];
                float4 tb2 = rb[lane + 64];
                a2.x += ta2.x; a2.y += ta2.y; a2.z += ta2.z; a2.w += ta2.w;
                b2.x += tb2.x; b2.y += tb2.y; b2.z += tb2.z; b2.w += tb2.w;
            }
        }

        #pragma unroll
        for (int s = 0; s < S; s++) {
            const float4* ra = (const float4*)(Ws + ((size_t)xa * S + s) * D);
            const float4* rb = (const float4*)(Ws + ((size_t)xb * S + s) * D);
            float4 ta0 = ra[lane];
            float4 tb0 = rb[lane];
            float4 ta1 = ra[lane + 32];
            float4 tb1 = rb[lane + 32];
            // scores for both elements sum directly (output reduces over batch)
            float p = ta0.x*a0.x + ta0.y*a0.y + ta0.z*a0.z + ta0.w*a0.w
                    + tb0.x*b0.x + tb0.y*b0.y + tb0.z*b0.z + tb0.w*b0.w
                    + ta1.x*a1.x + ta1.y*a1.y + ta1.z*a1.z + ta1.w*a1.w
                    + tb1.x*b1.x + tb1.y*b1.y + tb1.z*b1.z + tb1.w*b1.w;
            if (has3) {
                float4 ta2 = ra[lane + 64];
                float4 tb2 = rb[lane + 64];
                p += ta2.x*a2.x + ta2.y*a2.y + ta2.z*a2.z + ta2.w*a2.w
                   + tb2.x*b2.x + tb2.y*b2.y + tb2.z*b2.z + tb2.w*b2.w;
            }
            #pragma unroll
            for (int o = 16; o > 0; o >>= 1)
                p += __shfl_xor_sync(0xFFFFFFFFu, p, o);
            sc[s] = p;
        }
    }

    // block combine via shared atomics (8 warps x 5)
    if (lane == 0) {
        #pragma unroll
        for (int s = 0; s < S; s++)
            atomicAdd(&ssum[s], sc[s]);
    }
    __syncthreads();

    // one global atomicAdd per block per sense (5120 total to 5 addresses)
    if (threadIdx.x < S)
        atomicAdd(&g_acc[threadIdx.x], ssum[threadIdx.x]);
}

__global__ void finalize_kernel(float* __restrict__ out) {
    if (threadIdx.x < S) {
        float v = g_acc[threadIdx.x];
        out[threadIdx.x] = 1.0f / (1.0f + expf(-v));
        g_acc[threadIdx.x] = 0.0f;   // reset for next call / graph replay
    }
}

extern "C" void kernel_launch(void* const* d_in, const int* in_sizes, int n_in,
                              void* d_out, int out_size) {
    const int*   x  = (const int*)d_in[0];
    const float* Wg = (const float*)d_in[1];
    const float* Ws = (const float*)d_in[2];
    float* out = (float*)d_out;

    sense_main_kernel<<<NBLOCKS, THREADS>>>(x, Wg, Ws);
    finalize_kernel<<<1, 32>>>(out);
}

// round 9
// speedup vs baseline: 1.0536x; 1.0536x over previous
#include <cuda_runtime.h>
#include <math.h>

#define VOCAB 50000
#define D 300
#define S 5
#define CTX 10
#define B 16384
#define XCOLS (2 + CTX)

#define THREADS 128
#define NBLOCKS (B * 32 / THREADS)   // one warp per batch element -> 4096 blocks

// Zero at module load; finalize resets after each read -> graph-replay safe.
__device__ float g_acc[S];

__global__ __launch_bounds__(THREADS) void sense_main_kernel(
    const int* __restrict__ x,
    const float* __restrict__ Wg,
    const float* __restrict__ Ws)
{
    const int gwarp = (blockIdx.x * THREADS + threadIdx.x) >> 5;
    const int lane  = threadIdx.x & 31;

    __shared__ float ssum[S];
    if (threadIdx.x < S) ssum[threadIdx.x] = 0.0f;
    __syncthreads();

    float p[S] = {0.f, 0.f, 0.f, 0.f, 0.f};

    {
        // x row is 12 ints = 48 B, and 48 is a multiple of 16 -> int4-aligned.
        const int4* xq = (const int4*)(x + (size_t)gwarp * XCOLS);
        const int4 q0 = __ldg(&xq[0]);   // x0, x1, c0, c1
        const int4 q1 = __ldg(&xq[1]);   // c2..c5
        const int4 q2 = __ldg(&xq[2]);   // c6..c9
        const int x0 = q0.x;
        int w[CTX] = {q0.z, q0.w, q1.x, q1.y, q1.z, q1.w, q2.x, q2.y, q2.z, q2.w};

        // Precompute all 15 row base pointers (addresses independent of data).
        const float4* gr[CTX];
        #pragma unroll
        for (int j = 0; j < CTX; j++)
            gr[j] = (const float4*)(Wg + (size_t)w[j] * D);
        const float4* sr[S];
        #pragma unroll
        for (int s = 0; s < S; s++)
            sr[s] = (const float4*)(Ws + ((size_t)x0 * S + s) * D);

        // Chunk-major: per chunk, issue all 15 independent LDG.128s, then compute.
        #pragma unroll
        for (int c = 0; c < 3; c++) {
            const int off = c * 32 + lane;
            const bool act = (off < 75);           // 75 float4 per 300-float row
            float4 tg[CTX];
            float4 ts[S];
            #pragma unroll
            for (int j = 0; j < CTX; j++)
                tg[j] = act ? gr[j][off] : make_float4(0.f, 0.f, 0.f, 0.f);
            #pragma unroll
            for (int s = 0; s < S; s++)
                ts[s] = act ? sr[s][off] : make_float4(0.f, 0.f, 0.f, 0.f);

            float4 ctx = tg[0];
            #pragma unroll
            for (int j = 1; j < CTX; j++) {
                ctx.x += tg[j].x; ctx.y += tg[j].y;
                ctx.z += tg[j].z; ctx.w += tg[j].w;
            }
            #pragma unroll
            for (int s = 0; s < S; s++)
                p[s] += ts[s].x * ctx.x + ts[s].y * ctx.y
                      + ts[s].z * ctx.z + ts[s].w * ctx.w;
        }
    }

    // warp reduce each sense score
    #pragma unroll
    for (int s = 0; s < S; s++) {
        float v = p[s];
        #pragma unroll
        for (int o = 16; o > 0; o >>= 1)
            v += __shfl_xor_sync(0xFFFFFFFFu, v, o);
        p[s] = v;
    }

    // block combine via shared atomics (4 warps x 5)
    if (lane == 0) {
        #pragma unroll
        for (int s = 0; s < S; s++)
            atomicAdd(&ssum[s], p[s]);
    }
    __syncthreads();

    // one global atomicAdd per block per sense (20480 total to 5 addresses)
    if (threadIdx.x < S)
        atomicAdd(&g_acc[threadIdx.x], ssum[threadIdx.x]);
}

__global__ void finalize_kernel(float* __restrict__ out) {
    if (threadIdx.x < S) {
        float v = g_acc[threadIdx.x];
        out[threadIdx.x] = 1.0f / (1.0f + expf(-v));
        g_acc[threadIdx.x] = 0.0f;   // reset for next call / graph replay
    }
}

extern "C" void kernel_launch(void* const* d_in, const int* in_sizes, int n_in,
                              void* d_out, int out_size) {
    const int*   x  = (const int*)d_in[0];
    const float* Wg = (const float*)d_in[1];
    const float* Ws = (const float*)d_in[2];
    float* out = (float*)d_out;

    sense_main_kernel<<<NBLOCKS, THREADS>>>(x, Wg, Ws);
    finalize_kernel<<<1, 32>>>(out);
}

// round 10
// speedup vs baseline: 1.0608x; 1.0069x over previous
#include <cuda_runtime.h>
#include <math.h>

#define VOCAB 50000
#define D 300
#define S 5
#define CTX 10
#define B 16384
#define XCOLS (2 + CTX)

#define THREADS 128
#define NBLOCKS (B * 32 / THREADS)   // one warp per batch element -> 4096 blocks

// Zero at module load; finalize resets after each read -> graph-replay safe.
__device__ float g_acc[S];

__global__ __launch_bounds__(THREADS) void sense_main_kernel(
    const int* __restrict__ x,
    const float* __restrict__ Wg,
    const float* __restrict__ Ws)
{
    const int gwarp = (blockIdx.x * THREADS + threadIdx.x) >> 5;
    const int lane  = threadIdx.x & 31;

    __shared__ float ssum[S];
    if (threadIdx.x < S) ssum[threadIdx.x] = 0.0f;
    __syncthreads();

    float p[S] = {0.f, 0.f, 0.f, 0.f, 0.f};

    {
        // x row is 12 ints = 48 B, and 48 is a multiple of 16 -> int4-aligned.
        const int4* xq = (const int4*)(x + (size_t)gwarp * XCOLS);
        const int4 q0 = __ldg(&xq[0]);   // x0, x1, c0, c1
        const int4 q1 = __ldg(&xq[1]);   // c2..c5
        const int4 q2 = __ldg(&xq[2]);   // c6..c9
        const int x0 = q0.x;
        int w[CTX] = {q0.z, q0.w, q1.x, q1.y, q1.z, q1.w, q2.x, q2.y, q2.z, q2.w};

        // Precompute all 15 row base pointers (addresses independent of data).
        const float4* gr[CTX];
        #pragma unroll
        for (int j = 0; j < CTX; j++)
            gr[j] = (const float4*)(Wg + (size_t)w[j] * D);
        const float4* sr[S];
        #pragma unroll
        for (int s = 0; s < S; s++)
            sr[s] = (const float4*)(Ws + ((size_t)x0 * S + s) * D);

        // Chunk-major: per chunk, issue all 15 independent LDG.128s, then compute.
        #pragma unroll
        for (int c = 0; c < 3; c++) {
            const int off = c * 32 + lane;
            const bool act = (off < 75);           // 75 float4 per 300-float row
            float4 tg[CTX];
            float4 ts[S];
            #pragma unroll
            for (int j = 0; j < CTX; j++)
                tg[j] = act ? gr[j][off] : make_float4(0.f, 0.f, 0.f, 0.f);
            #pragma unroll
            for (int s = 0; s < S; s++)
                ts[s] = act ? sr[s][off] : make_float4(0.f, 0.f, 0.f, 0.f);

            float4 ctx = tg[0];
            #pragma unroll
            for (int j = 1; j < CTX; j++) {
                ctx.x += tg[j].x; ctx.y += tg[j].y;
                ctx.z += tg[j].z; ctx.w += tg[j].w;
            }
            #pragma unroll
            for (int s = 0; s < S; s++)
                p[s] += ts[s].x * ctx.x + ts[s].y * ctx.y
                      + ts[s].z * ctx.z + ts[s].w * ctx.w;
        }
    }

    // warp reduce each sense score
    #pragma unroll
    for (int s = 0; s < S; s++) {
        float v = p[s];
        #pragma unroll
        for (int o = 16; o > 0; o >>= 1)
            v += __shfl_xor_sync(0xFFFFFFFFu, v, o);
        p[s] = v;
    }

    // block combine via shared atomics (4 warps x 5)
    if (lane == 0) {
        #pragma unroll
        for (int s = 0; s < S; s++)
            atomicAdd(&ssum[s], p[s]);
    }
    __syncthreads();

    // one global atomicAdd per block per sense (20480 total to 5 addresses)
    if (threadIdx.x < S)
        atomicAdd(&g_acc[threadIdx.x], ssum[threadIdx.x]);
}

__global__ void finalize_kernel(float* __restrict__ out) {
    // PDL: this kernel launches while sense_main_kernel drains; block here
    // until the primary grid's memory ops (g_acc atomics) are visible.
    cudaGridDependencySynchronize();
    if (threadIdx.x < S) {
        float v = g_acc[threadIdx.x];
        out[threadIdx.x] = 1.0f / (1.0f + expf(-v));
        g_acc[threadIdx.x] = 0.0f;   // reset for next call / graph replay
    }
}

extern "C" void kernel_launch(void* const* d_in, const int* in_sizes, int n_in,
                              void* d_out, int out_size) {
    const int*   x  = (const int*)d_in[0];
    const float* Wg = (const float*)d_in[1];
    const float* Ws = (const float*)d_in[2];
    float* out = (float*)d_out;

    sense_main_kernel<<<NBLOCKS, THREADS>>>(x, Wg, Ws);

    // Programmatic dependent launch: overlap finalize's launch latency with
    // the primary kernel's tail.
    cudaLaunchAttribute attrs[1];
    attrs[0].id = cudaLaunchAttributeProgrammaticStreamSerialization;
    attrs[0].val.programmaticStreamSerializationAllowed = 1;

    cudaLaunchConfig_t cfg = {};
    cfg.gridDim = dim3(1, 1, 1);
    cfg.blockDim = dim3(32, 1, 1);
    cfg.dynamicSmemBytes = 0;
    cfg.stream = 0;               // legacy default stream (same as <<<>>> above)
    cfg.attrs = attrs;
    cfg.numAttrs = 1;

    cudaLaunchKernelEx(&cfg, finalize_kernel, out);
}